// round 14
// baseline (speedup 1.0000x reference)
#include <cuda_runtime.h>
#include <cuda_fp16.h>
#include <math.h>

#define NNODE 30000
#define NEDGE 300000
#define ETOT  330000
#define NB    300
#define EMB   64
#define D1    256
#define H12   4
#define H3    6
#define OUT3  121
#define D3    726
#define D3P   768
#define NCLS  10

// ---------------- scratch ----------------------------------------------------
__device__ __half g_x0h  [NNODE * EMB];
__device__ __half g_p1h  [NNODE * D1];
__device__ __half g_feath[NNODE * D1];
__device__ __half g_projh[NNODE * D1];
__device__ __half g_feat2h[NNODE * D1];
__device__ __half g_agg3h[NNODE * (H3 * D1)];
__device__ float  g_es  [NNODE * H3];
__device__ float  g_ed  [NNODE * H3];
__device__ float  g_va1[H12 * EMB], g_vd1[H12 * EMB];
__device__ float  g_va2[H12 * D1],  g_vd2[H12 * D1];
__device__ float  g_va3[H3 * D1],   g_vd3[H3 * D1];
__device__ __half g_w1t[H12 * 64 * 64];
__device__ __half g_w2t[D1 * D1];
__device__ __half g_w3t[H3 * 128 * D1];
__device__ float  g_b3p[D3P];
__device__ float  g_poolx[NB * H3 * D1];   // per-graph summed aggregated x
__device__ float  g_pool[NB * D3P];        // projected pooled output
__device__ int    g_deg [NNODE];
__device__ int    g_off [NNODE + 1];
__device__ int    g_goff[NB + 1];
__device__ int    g_cur [NNODE];
__device__ int    g_csrc[ETOT];
__device__ int    g_bsum[32];
__device__ int    g_bpre[32];

// ---------------- fused setup: node_enc + count_deg + goff + weights + va ----
#define SETUP_A (NNODE * EMB)
#define SETUP_B ETOT
#define SETUP_C NNODE
#define SETUP_D (16384 + 65536 + H3 * 128 * D1)
#define SETUP_E (H12 * EMB + H12 * D1 + H3 * D1)
#define SETUP_TOTAL (SETUP_A + SETUP_B + SETUP_C + SETUP_D + SETUP_E)

__global__ void setup_all(const int* __restrict__ x, const int* __restrict__ nd,
                          const float* __restrict__ ne, const float* __restrict__ de,
                          const int* __restrict__ ei, const int* __restrict__ bat,
                          const float* __restrict__ w1, const float* __restrict__ as1, const float* __restrict__ ad1,
                          const float* __restrict__ w2, const float* __restrict__ as2, const float* __restrict__ ad2,
                          const float* __restrict__ w3, const float* __restrict__ as3, const float* __restrict__ ad3,
                          const float* __restrict__ b3,
                          __half* __restrict__ x0h, int* __restrict__ deg, int* __restrict__ goff,
                          __half* __restrict__ w1t, __half* __restrict__ w2t, __half* __restrict__ w3t,
                          float* __restrict__ b3p,
                          float* __restrict__ va1, float* __restrict__ vd1,
                          float* __restrict__ va2, float* __restrict__ vd2,
                          float* __restrict__ va3, float* __restrict__ vd3) {
    int gid = blockIdx.x * blockDim.x + threadIdx.x;
    if (gid < SETUP_A) {
        int n = gid >> 6, d = gid & 63;
        x0h[gid] = __float2half(ne[x[n] * EMB + d] + de[nd[n] * EMB + d]);
        return;
    }
    gid -= SETUP_A;
    if (gid < SETUP_B) {
        int d = (gid < NEDGE) ? ei[NEDGE + gid] : gid - NEDGE;
        atomicAdd(&deg[d], 1);
        return;
    }
    gid -= SETUP_B;
    if (gid < SETUP_C) {            // graph offsets from sorted batch
        int n = gid;
        int c = bat[n];
        if (n == 0) { for (int g = 0; g <= c; g++) goff[g] = 0; }
        else { int p = bat[n - 1]; for (int g = p + 1; g <= c; g++) goff[g] = n; }
        if (n == NNODE - 1) { for (int g = c + 1; g <= NB; g++) goff[g] = NNODE; }
        return;
    }
    gid -= SETUP_C;
    if (gid < SETUP_D) {
        int i = gid;
        if (i < 16384) {
            int h = i >> 12, r = i & 4095, n = r >> 6, k = r & 63;
            w1t[i] = __float2half(w1[k * D1 + h * 64 + n]);
        }
        int j = i - 16384;
        if (j >= 0 && j < 65536) {
            int n = j >> 8, k = j & 255;
            w2t[j] = __float2half(w2[k * D1 + n]);
        }
        int q = i - (16384 + 65536);
        if (q >= 0 && q < H3 * 128 * D1) {
            int h = q >> 15, r = q & 32767, n = r >> 8, k = r & 255;
            w3t[q] = __float2half(n < OUT3 ? w3[k * D3 + h * OUT3 + n] : 0.f);
        }
        if (i < D3P) {
            int h = i >> 7, o = i & 127;
            b3p[i] = (o < OUT3) ? b3[h * OUT3 + o] : 0.f;
        }
        return;
    }
    gid -= SETUP_D;
    if (gid < H12 * EMB) {
        int h = gid >> 6, k = gid & 63;
        float s1 = 0.f, s2 = 0.f;
        for (int d = 0; d < EMB; d++) {
            float w = w1[k * D1 + h * EMB + d];
            s1 += w * as1[h * EMB + d];
            s2 += w * ad1[h * EMB + d];
        }
        va1[gid] = s1; vd1[gid] = s2;
        return;
    }
    gid -= H12 * EMB;
    if (gid < H12 * D1) {
        int h = gid >> 8, k = gid & 255;
        float s1 = 0.f, s2 = 0.f;
        for (int d = 0; d < EMB; d++) {
            float w = w2[k * D1 + h * EMB + d];
            s1 += w * as2[h * EMB + d];
            s2 += w * ad2[h * EMB + d];
        }
        va2[gid] = s1; vd2[gid] = s2;
        return;
    }
    gid -= H12 * D1;
    if (gid < H3 * D1) {
        int h = gid >> 8, k = gid & 255;
        float s1 = 0.f, s2 = 0.f;
        for (int o = 0; o < OUT3; o++) {
            float w = w3[k * D3 + h * OUT3 + o];
            s1 += w * as3[h * OUT3 + o];
            s2 += w * ad3[h * OUT3 + o];
        }
        va3[gid] = s1; vd3[gid] = s2;
    }
}

// ---------------- CSR scan chain ---------------------------------------------
__global__ __launch_bounds__(1024) void deg_part(const int* __restrict__ deg,
                                                 int* __restrict__ bsum) {
    __shared__ int ws[32];
    int t = threadIdx.x, lane = t & 31, w = t >> 5;
    int idx = blockIdx.x * 1024 + t;
    int v = (idx < NNODE) ? deg[idx] : 0;
#pragma unroll
    for (int o = 16; o; o >>= 1) v += __shfl_xor_sync(0xffffffffu, v, o);
    if (lane == 0) ws[w] = v;
    __syncthreads();
    if (t < 32) {
        int s = ws[t];
#pragma unroll
        for (int o = 16; o; o >>= 1) s += __shfl_xor_sync(0xffffffffu, s, o);
        if (t == 0) bsum[blockIdx.x] = s;
    }
}
__global__ void scan_bsum(const int* __restrict__ bsum, int* __restrict__ bpre,
                          int* __restrict__ off, int nblk) {
    int t = threadIdx.x;
    int v = (t < nblk) ? bsum[t] : 0;
    int own = v;
#pragma unroll
    for (int o = 1; o < 32; o <<= 1) {
        int y = __shfl_up_sync(0xffffffffu, v, o);
        if (t >= o) v += y;
    }
    if (t < nblk) bpre[t] = v - own;
    if (t == 31) off[NNODE] = v;
}
__global__ __launch_bounds__(1024) void deg_scan(const int* __restrict__ deg,
                                                 const int* __restrict__ bpre,
                                                 int* __restrict__ off) {
    __shared__ int ws[32];
    int t = threadIdx.x, lane = t & 31, w = t >> 5;
    int idx = blockIdx.x * 1024 + t;
    int v = (idx < NNODE) ? deg[idx] : 0;
    int x = v;
#pragma unroll
    for (int o = 1; o < 32; o <<= 1) {
        int y = __shfl_up_sync(0xffffffffu, x, o);
        if (lane >= o) x += y;
    }
    if (lane == 31) ws[w] = x;
    __syncthreads();
    if (w == 0) {
        int y = ws[lane];
#pragma unroll
        for (int o = 1; o < 32; o <<= 1) {
            int z = __shfl_up_sync(0xffffffffu, y, o);
            if (lane >= o) y += z;
        }
        ws[lane] = y;
    }
    __syncthreads();
    int excl = x - v + (w ? ws[w - 1] : 0) + bpre[blockIdx.x];
    if (idx < NNODE) off[idx] = excl;
}
__global__ void scatter_edges(const int* __restrict__ ei, const int* __restrict__ off,
                              int* __restrict__ cur, int* __restrict__ csrc) {
    int e = blockIdx.x * blockDim.x + threadIdx.x;
    if (e >= ETOT) return;
    int s, d;
    if (e < NEDGE) { s = ei[e]; d = ei[NEDGE + e]; }
    else           { s = d = e - NEDGE; }
    int slot = off[d] + atomicAdd(&cur[d], 1);
    csrc[slot] = s;
}

// ---------------- fp16 tensor GEMM: C = A @ Bt^T -----------------------------
template <int BN>
__global__ __launch_bounds__(256) void gemm_h16(
        const __half* __restrict__ A, const __half* __restrict__ Bt,
        __half* __restrict__ Ch, const float* __restrict__ bias,
        int M, int K, int lda, int ldb, int ldc,
        int aHS, int bHS, int cHS, int biasHS, int elu) {
    constexpr int AST = 40;
    constexpr int WN = BN / 2;
    constexpr int JT = WN / 8;
    __shared__ __half As[128 * AST];
    __shared__ __half Bs[BN * AST];
    int t = threadIdx.x;
    int warp = t >> 5, lane = t & 31;
    int tg = lane >> 2, t4 = lane & 3;
    int bm = blockIdx.y * 128, bn = blockIdx.x * BN;
    int z = blockIdx.z;
    const __half* Az = A + (size_t)aHS * z;
    const __half* Bz = Bt + (size_t)bHS * z;
    int wm = (warp & 3) * 32, wn = (warp >> 2) * WN;
    float c[2][JT][4];
#pragma unroll
    for (int i = 0; i < 2; i++)
#pragma unroll
        for (int j = 0; j < JT; j++)
#pragma unroll
            for (int q = 0; q < 4; q++) c[i][j][q] = 0.f;

    for (int k0 = 0; k0 < K; k0 += 32) {
#pragma unroll
        for (int i = 0; i < 2; i++) {
            int v = t + 256 * i;
            int row = v >> 2, kc = (v & 3) * 8;
            uint4 u = make_uint4(0u, 0u, 0u, 0u);
            int gr = bm + row;
            if (gr < M) u = *(const uint4*)(Az + (size_t)gr * lda + k0 + kc);
            *(uint4*)&As[row * AST + kc] = u;
        }
#pragma unroll
        for (int i = 0; i < BN / 64; i++) {
            int v = t + 256 * i;
            int row = v >> 2, kc = (v & 3) * 8;
            *(uint4*)&Bs[row * AST + kc] =
                *(const uint4*)(Bz + (size_t)(bn + row) * ldb + k0 + kc);
        }
        __syncthreads();
#pragma unroll
        for (int ks = 0; ks < 2; ks++) {
            int kb = ks * 16;
            unsigned a[2][4], b[JT][2];
#pragma unroll
            for (int i = 0; i < 2; i++) {
                int r = wm + 16 * i + tg;
                a[i][0] = *(const unsigned*)&As[r * AST + kb + 2 * t4];
                a[i][1] = *(const unsigned*)&As[(r + 8) * AST + kb + 2 * t4];
                a[i][2] = *(const unsigned*)&As[r * AST + kb + 2 * t4 + 8];
                a[i][3] = *(const unsigned*)&As[(r + 8) * AST + kb + 2 * t4 + 8];
            }
#pragma unroll
            for (int j = 0; j < JT; j++) {
                int n = wn + 8 * j + tg;
                b[j][0] = *(const unsigned*)&Bs[n * AST + kb + 2 * t4];
                b[j][1] = *(const unsigned*)&Bs[n * AST + kb + 2 * t4 + 8];
            }
#pragma unroll
            for (int i = 0; i < 2; i++)
#pragma unroll
                for (int j = 0; j < JT; j++) {
                    asm volatile(
                        "mma.sync.aligned.m16n8k16.row.col.f32.f16.f16.f32 "
                        "{%0,%1,%2,%3}, {%4,%5,%6,%7}, {%8,%9}, {%0,%1,%2,%3};"
                        : "+f"(c[i][j][0]), "+f"(c[i][j][1]),
                          "+f"(c[i][j][2]), "+f"(c[i][j][3])
                        : "r"(a[i][0]), "r"(a[i][1]), "r"(a[i][2]), "r"(a[i][3]),
                          "r"(b[j][0]), "r"(b[j][1]));
                }
        }
        __syncthreads();
    }
#pragma unroll
    for (int i = 0; i < 2; i++)
#pragma unroll
        for (int j = 0; j < JT; j++) {
            int r = bm + wm + 16 * i + tg;
            int cc = bn + wn + 8 * j + 2 * t4;
            float v0 = c[i][j][0], v1 = c[i][j][1];
            float v2 = c[i][j][2], v3 = c[i][j][3];
            if (bias) {
                float b0 = bias[biasHS * z + cc], b1 = bias[biasHS * z + cc + 1];
                v0 += b0; v1 += b1; v2 += b0; v3 += b1;
            }
            if (elu) {
                v0 = v0 > 0.f ? v0 : expm1f(v0);
                v1 = v1 > 0.f ? v1 : expm1f(v1);
                v2 = v2 > 0.f ? v2 : expm1f(v2);
                v3 = v3 > 0.f ? v3 : expm1f(v3);
            }
            __half* Hz = Ch + (size_t)cHS * z;
            if (r < M)     *(__half2*)(Hz + (size_t)r * ldc + cc)       = __floats2half2_rn(v0, v1);
            if (r + 8 < M) *(__half2*)(Hz + (size_t)(r + 8) * ldc + cc) = __floats2half2_rn(v2, v3);
        }
}

// ---------------- attention logits: thread per node, fp16 rows ---------------
template <int K, int H>
__global__ __launch_bounds__(256) void attn_h(const __half* __restrict__ feat,
                                              const float* __restrict__ va,
                                              const float* __restrict__ vd,
                                              float* __restrict__ es,
                                              float* __restrict__ ed) {
    constexpr int K8 = K / 8;
    __shared__ float sva[H * K], svd[H * K];
    int t = threadIdx.x;
    for (int i = t; i < H * K; i += 256) { sva[i] = va[i]; svd[i] = vd[i]; }
    __syncthreads();
    int n = blockIdx.x * 256 + t;
    if (n >= NNODE) return;
    const __half* row = feat + (size_t)n * K;
    float e1[H], e2[H];
#pragma unroll
    for (int h = 0; h < H; h++) { e1[h] = 0.f; e2[h] = 0.f; }
    for (int k8 = 0; k8 < K8; k8++) {
        uint4 u = *(const uint4*)(row + k8 * 8);
        __half2 h0 = *(__half2*)&u.x, h1 = *(__half2*)&u.y;
        __half2 h2 = *(__half2*)&u.z, h3 = *(__half2*)&u.w;
        float xv[8];
        xv[0] = __low2float(h0); xv[1] = __high2float(h0);
        xv[2] = __low2float(h1); xv[3] = __high2float(h1);
        xv[4] = __low2float(h2); xv[5] = __high2float(h2);
        xv[6] = __low2float(h3); xv[7] = __high2float(h3);
#pragma unroll
        for (int h = 0; h < H; h++)
#pragma unroll
            for (int p = 0; p < 8; p++) {
                e1[h] += xv[p] * sva[h * K + k8 * 8 + p];
                e2[h] += xv[p] * svd[h * K + k8 * 8 + p];
            }
    }
#pragma unroll
    for (int h = 0; h < H; h++) {
        es[n * H + h] = e1[h];
        ed[n * H + h] = e2[h];
    }
}

// ---------------- single-pass per-head x aggregation (warp per node) --------
template <int H, int HPL>
__global__ __launch_bounds__(256) void gat_agg_xh(const int* __restrict__ off,
                                                  const int* __restrict__ csrc,
                                                  const float* __restrict__ es,
                                                  const float* __restrict__ ed,
                                                  const __half* __restrict__ xin,
                                                  __half* __restrict__ agg) {
    constexpr int KH = 32 * HPL;
    int gw = (blockIdx.x * blockDim.x + threadIdx.x) >> 5;
    int lane = threadIdx.x & 31;
    if (gw >= NNODE) return;
    int o0 = off[gw], o1 = off[gw + 1];
    float edv = (lane < H) ? __ldg(&ed[gw * H + lane]) : 0.f;
    float smv = 0.f;
    float acc[H][HPL];
#pragma unroll
    for (int h = 0; h < H; h++)
#pragma unroll
        for (int p = 0; p < HPL; p++) acc[h][p] = 0.f;

    for (int i = o0; i < o1; i++) {
        int s = __ldg(&csrc[i]);
        float a = 0.f;
        if (lane < H) {
            float v = __ldg(&es[s * H + lane]) + edv;
            v = v > 0.f ? v : 0.2f * v;
            a = __expf(v);
            smv += a;
        }
        float ah[H];
#pragma unroll
        for (int h = 0; h < H; h++) ah[h] = __shfl_sync(0xffffffffu, a, h);
        const __half* row = xin + (size_t)s * KH + lane * HPL;
        float xv[HPL];
        if (HPL == 2) {
            __half2 hv = *(const __half2*)row;
            xv[0] = __low2float(hv); xv[1] = __high2float(hv);
        } else {
            uint4 u = *(const uint4*)row;
            __half2 h0 = *(__half2*)&u.x, h1 = *(__half2*)&u.y;
            __half2 h2 = *(__half2*)&u.z, h3 = *(__half2*)&u.w;
            xv[0] = __low2float(h0); xv[1] = __high2float(h0);
            xv[2] = __low2float(h1); xv[3] = __high2float(h1);
            xv[4] = __low2float(h2); xv[5] = __high2float(h2);
            xv[6] = __low2float(h3); xv[7] = __high2float(h3);
        }
#pragma unroll
        for (int h = 0; h < H; h++)
#pragma unroll
            for (int p = 0; p < HPL; p++) acc[h][p] += ah[h] * xv[p];
    }
    float inv[H];
#pragma unroll
    for (int h = 0; h < H; h++)
        inv[h] = 1.f / __shfl_sync(0xffffffffu, smv, h);
    __half* orow = agg + (size_t)gw * (H * KH);
#pragma unroll
    for (int h = 0; h < H; h++)
#pragma unroll
        for (int p = 0; p < HPL; p += 2)
            *(__half2*)(orow + h * KH + lane * HPL + p) =
                __floats2half2_rn(acc[h][p] * inv[h], acc[h][p + 1] * inv[h]);
}

// ---------------- single-pass layer-2 aggregation (fp16 out) -----------------
__global__ __launch_bounds__(256) void gat_agg_ph(const int* __restrict__ off,
                                                  const int* __restrict__ csrc,
                                                  const float* __restrict__ es,
                                                  const float* __restrict__ ed,
                                                  const __half* __restrict__ proj,
                                                  const float* __restrict__ bias,
                                                  __half* __restrict__ outh) {
    constexpr int H = H12;
    int gw = (blockIdx.x * blockDim.x + threadIdx.x) >> 5;
    int lane = threadIdx.x & 31;
    if (gw >= NNODE) return;
    int o0 = off[gw], o1 = off[gw + 1];
    float edv = (lane < H) ? __ldg(&ed[gw * H + lane]) : 0.f;
    float smv = 0.f;
    float acc[8];
#pragma unroll
    for (int p = 0; p < 8; p++) acc[p] = 0.f;
    int myhead = lane >> 3;

    for (int i = o0; i < o1; i++) {
        int s = __ldg(&csrc[i]);
        float a = 0.f;
        if (lane < H) {
            float v = __ldg(&es[s * H + lane]) + edv;
            v = v > 0.f ? v : 0.2f * v;
            a = __expf(v);
            smv += a;
        }
        float av = __shfl_sync(0xffffffffu, a, myhead);
        uint4 u = *(const uint4*)(proj + (size_t)s * D1 + lane * 8);
        __half2 h0 = *(__half2*)&u.x, h1 = *(__half2*)&u.y;
        __half2 h2 = *(__half2*)&u.z, h3 = *(__half2*)&u.w;
        acc[0] += av * __low2float(h0); acc[1] += av * __high2float(h0);
        acc[2] += av * __low2float(h1); acc[3] += av * __high2float(h1);
        acc[4] += av * __low2float(h2); acc[5] += av * __high2float(h2);
        acc[6] += av * __low2float(h3); acc[7] += av * __high2float(h3);
    }
    float inv = 1.f / __shfl_sync(0xffffffffu, smv, myhead);
    __half* hrow = outh + (size_t)gw * D1 + lane * 8;
#pragma unroll
    for (int p = 0; p < 8; p += 2) {
        float v0 = acc[p] * inv + bias[lane * 8 + p];
        float v1 = acc[p + 1] * inv + bias[lane * 8 + p + 1];
        v0 = v0 > 0.f ? v0 : expm1f(v0);
        v1 = v1 > 0.f ? v1 : expm1f(v1);
        *(__half2*)(hrow + p) = __floats2half2_rn(v0, v1);
    }
}

// ---------------- streaming per-graph pool of agg3h --------------------------
// block per graph, 256 threads; thread t owns columns t, t+256, ... (6 of 1536)
__global__ __launch_bounds__(256) void pool_seg(const int* __restrict__ goff,
                                                const __half* __restrict__ agg,
                                                float* __restrict__ poolx) {
    constexpr int NCOL = H3 * D1;    // 1536
    int b = blockIdx.x;
    int t = threadIdx.x;
    int n0 = goff[b], n1 = goff[b + 1];
    float acc[NCOL / 256];           // 6
#pragma unroll
    for (int j = 0; j < NCOL / 256; j++) acc[j] = 0.f;
    for (int n = n0; n < n1; n++) {
        const __half* row = agg + (size_t)n * NCOL;
#pragma unroll
        for (int j = 0; j < NCOL / 256; j++)
            acc[j] += __half2float(__ldg(&row[t + 256 * j]));
    }
    float* orow = poolx + (size_t)b * NCOL;
#pragma unroll
    for (int j = 0; j < NCOL / 256; j++) orow[t + 256 * j] = acc[j];
}

// ---------------- tiny projection: poolx [NB,6,256] @ w3t -> pool [NB,768] ---
__global__ __launch_bounds__(256) void proj_pool(const float* __restrict__ poolx,
                                                 const __half* __restrict__ w3t,
                                                 float* __restrict__ pool) {
    int h = blockIdx.x;
    int r0 = blockIdx.y * 128;
    int t = threadIdx.x;
    int c = t & 127, rg = t >> 7;
    const __half* wrow = w3t + (size_t)h * (128 * D1) + (size_t)c * D1;
    for (int r = r0 + rg; r < NB && r < r0 + 128; r += 2) {
        const float* px = poolx + (size_t)r * (H3 * D1) + h * D1;
        float acc = 0.f;
        for (int k = 0; k < D1; k += 8) {
            uint4 w = *(const uint4*)(wrow + k);
            __half2 w0 = *(__half2*)&w.x, w1 = *(__half2*)&w.y;
            __half2 w2 = *(__half2*)&w.z, w3 = *(__half2*)&w.w;
            float4 p0 = *(const float4*)(px + k);
            float4 p1 = *(const float4*)(px + k + 4);
            acc += p0.x * __low2float(w0) + p0.y * __high2float(w0)
                 + p0.z * __low2float(w1) + p0.w * __high2float(w1)
                 + p1.x * __low2float(w2) + p1.y * __high2float(w2)
                 + p1.z * __low2float(w3) + p1.w * __high2float(w3);
        }
        pool[(size_t)r * D3P + h * 128 + c] = acc;
    }
}

// ---------------- classifier head --------------------------------------------
__global__ void head_kernel(const float* __restrict__ pool, const int* __restrict__ goff,
                            const float* __restrict__ b3p,
                            const float* __restrict__ wp, const float* __restrict__ bp,
                            float* __restrict__ out) {
    __shared__ float gm[OUT3];
    int b = blockIdx.x;
    float cn = (float)(goff[b + 1] - goff[b]);
    float inv = 1.f / fmaxf(cn, 1.f);
    for (int o = threadIdx.x; o < OUT3; o += blockDim.x) {
        float s = 0.f, sb = 0.f;
#pragma unroll
        for (int h = 0; h < H3; h++) {
            s += pool[b * D3P + h * 128 + o];
            sb += b3p[h * 128 + o];
        }
        gm[o] = (s * inv + sb) * (1.f / H3);
    }
    __syncthreads();
    if (threadIdx.x < NCLS) {
        float acc = bp[threadIdx.x];
        for (int o = 0; o < OUT3; o++) acc += gm[o] * wp[o * NCLS + threadIdx.x];
        out[b * NCLS + threadIdx.x] = acc;
    }
}

// ---------------- host orchestration ----------------------------------------
extern "C" void kernel_launch(void* const* d_in, const int* in_sizes, int n_in,
                              void* d_out, int out_size) {
    const int*   x    = (const int*)d_in[0];
    const int*   nd   = (const int*)d_in[1];
    const int*   ei   = (const int*)d_in[2];
    const int*   bat  = (const int*)d_in[3];
    const float* nemb = (const float*)d_in[4];
    const float* demb = (const float*)d_in[5];
    const float* w1   = (const float*)d_in[6];
    const float* as1  = (const float*)d_in[7];
    const float* ad1  = (const float*)d_in[8];
    const float* b1   = (const float*)d_in[9];
    const float* w2   = (const float*)d_in[10];
    const float* as2  = (const float*)d_in[11];
    const float* ad2  = (const float*)d_in[12];
    const float* b2   = (const float*)d_in[13];
    const float* w3   = (const float*)d_in[14];
    const float* as3  = (const float*)d_in[15];
    const float* ad3  = (const float*)d_in[16];
    const float* b3   = (const float*)d_in[17];
    const float* wp   = (const float*)d_in[18];
    const float* bp   = (const float*)d_in[19];
    float* out = (float*)d_out;

    float *es, *ed, *va1, *vd1, *va2, *vd2, *va3, *vd3, *b3p, *poolx, *pool;
    __half *x0h, *p1h, *feath, *projh, *feat2h, *agg3h, *w1t, *w2t, *w3t;
    int *deg, *off, *goff, *cur, *csrc, *bsum, *bpre;
    cudaGetSymbolAddress((void**)&x0h,   g_x0h);
    cudaGetSymbolAddress((void**)&p1h,   g_p1h);
    cudaGetSymbolAddress((void**)&feath, g_feath);
    cudaGetSymbolAddress((void**)&projh, g_projh);
    cudaGetSymbolAddress((void**)&feat2h,g_feat2h);
    cudaGetSymbolAddress((void**)&agg3h, g_agg3h);
    cudaGetSymbolAddress((void**)&es,    g_es);
    cudaGetSymbolAddress((void**)&ed,    g_ed);
    cudaGetSymbolAddress((void**)&va1,   g_va1);
    cudaGetSymbolAddress((void**)&vd1,   g_vd1);
    cudaGetSymbolAddress((void**)&va2,   g_va2);
    cudaGetSymbolAddress((void**)&vd2,   g_vd2);
    cudaGetSymbolAddress((void**)&va3,   g_va3);
    cudaGetSymbolAddress((void**)&vd3,   g_vd3);
    cudaGetSymbolAddress((void**)&w1t,   g_w1t);
    cudaGetSymbolAddress((void**)&w2t,   g_w2t);
    cudaGetSymbolAddress((void**)&w3t,   g_w3t);
    cudaGetSymbolAddress((void**)&b3p,   g_b3p);
    cudaGetSymbolAddress((void**)&poolx, g_poolx);
    cudaGetSymbolAddress((void**)&pool,  g_pool);
    cudaGetSymbolAddress((void**)&deg,   g_deg);
    cudaGetSymbolAddress((void**)&off,   g_off);
    cudaGetSymbolAddress((void**)&goff,  g_goff);
    cudaGetSymbolAddress((void**)&cur,   g_cur);
    cudaGetSymbolAddress((void**)&csrc,  g_csrc);
    cudaGetSymbolAddress((void**)&bsum,  g_bsum);
    cudaGetSymbolAddress((void**)&bpre,  g_bpre);

    const int TB = 256;
    const int eb = (ETOT + TB - 1) / TB;
    const int nb = (NNODE * 32 + TB - 1) / TB;   // warp per node
    const int hb = (NNODE + TB - 1) / TB;        // thread per node
    const int SB = (NNODE + 1023) / 1024;
    const int MB = (NNODE + 127) / 128;

    cudaMemsetAsync(deg, 0, NNODE * 4);
    cudaMemsetAsync(cur, 0, NNODE * 4);

    setup_all<<<(SETUP_TOTAL + TB - 1) / TB, TB>>>(
        x, nd, nemb, demb, ei, bat,
        w1, as1, ad1, w2, as2, ad2, w3, as3, ad3, b3,
        x0h, deg, goff, w1t, w2t, w3t, b3p,
        va1, vd1, va2, vd2, va3, vd3);
    deg_part<<<SB, 1024>>>(deg, bsum);
    scan_bsum<<<1, 32>>>(bsum, bpre, off, SB);
    deg_scan<<<SB, 1024>>>(deg, bpre, off);
    scatter_edges<<<eb, TB>>>(ei, off, cur, csrc);

    // ---- layer 1 ----
    attn_h<EMB, H12><<<hb, TB>>>(x0h, va1, vd1, es, ed);
    gat_agg_xh<H12, 2><<<nb, TB>>>(off, csrc, es, ed, x0h, p1h);
    {
        dim3 g(1, MB, H12);
        gemm_h16<64><<<g, 256>>>(p1h, w1t, feath, b1, NNODE, EMB,
                                 D1, EMB, D1, EMB, 64 * EMB, EMB, EMB, 1);
    }

    // ---- layer 2 ----
    {
        dim3 g(2, MB, 1);
        gemm_h16<128><<<g, 256>>>(feath, w2t, projh, nullptr, NNODE, D1,
                                  D1, D1, D1, 0, 0, 0, 0, 0);
    }
    attn_h<D1, H12><<<hb, TB>>>(feath, va2, vd2, es, ed);
    gat_agg_ph<<<nb, TB>>>(off, csrc, es, ed, projh, b2, feat2h);

    // ---- layer 3: warp-per-node aggregate, streaming pool, tiny GEMM ----
    attn_h<D1, H3><<<hb, TB>>>(feat2h, va3, vd3, es, ed);
    gat_agg_xh<H3, 8><<<nb, TB>>>(off, csrc, es, ed, feat2h, agg3h);
    pool_seg<<<NB, TB>>>(goff, agg3h, poolx);
    {
        dim3 g(H3, (NB + 127) / 128);
        proj_pool<<<g, 256>>>(poolx, w3t, pool);
    }

    // ---- classifier head ----
    head_kernel<<<NB, 128>>>(pool, goff, b3p, wp, bp, out);
}

// round 15
// speedup vs baseline: 2.0202x; 2.0202x over previous
#include <cuda_runtime.h>
#include <cuda_fp16.h>
#include <math.h>

#define NNODE 30000
#define NEDGE 300000
#define ETOT  330000
#define NB    300
#define EMB   64
#define D1    256
#define H12   4
#define H3    6
#define OUT3  121
#define D3    726
#define D3P   768
#define NCLS  10

// ---------------- scratch ----------------------------------------------------
__device__ __half g_x0h  [NNODE * EMB];
__device__ __half g_p1h  [NNODE * D1];
__device__ __half g_feath[NNODE * D1];
__device__ __half g_projh[NNODE * D1];
__device__ __half g_feat2h[NNODE * D1];
__device__ __half g_agg3h[NNODE * (H3 * D1)];
__device__ float  g_es  [NNODE * H3];
__device__ float  g_ed  [NNODE * H3];
__device__ float  g_va1[H12 * EMB], g_vd1[H12 * EMB];
__device__ float  g_va2[H12 * D1],  g_vd2[H12 * D1];
__device__ float  g_va3[H3 * D1],   g_vd3[H3 * D1];
__device__ __half g_w1t[H12 * 64 * 64];
__device__ __half g_w2t[D1 * D1];
__device__ __half g_w3t[H3 * 128 * D1];
__device__ float  g_b3p[D3P];
__device__ float  g_poolx[NB * H3 * D1];
__device__ float  g_pool[NB * D3P];
__device__ int    g_deg [NNODE];
__device__ int    g_off [NNODE + 1];
__device__ int    g_goff[NB + 1];
__device__ int    g_cur [NNODE];
__device__ int    g_csrc[ETOT];
__device__ int    g_bsum[32];
__device__ int    g_bpre[32];

// ---------------- fused setup ------------------------------------------------
#define SETUP_A (NNODE * EMB)
#define SETUP_B ETOT
#define SETUP_C NNODE
#define SETUP_D (16384 + 65536 + H3 * 128 * D1)
#define SETUP_E (H12 * EMB + H12 * D1 + H3 * D1)
#define SETUP_TOTAL (SETUP_A + SETUP_B + SETUP_C + SETUP_D + SETUP_E)

__global__ void setup_all(const int* __restrict__ x, const int* __restrict__ nd,
                          const float* __restrict__ ne, const float* __restrict__ de,
                          const int* __restrict__ ei, const int* __restrict__ bat,
                          const float* __restrict__ w1, const float* __restrict__ as1, const float* __restrict__ ad1,
                          const float* __restrict__ w2, const float* __restrict__ as2, const float* __restrict__ ad2,
                          const float* __restrict__ w3, const float* __restrict__ as3, const float* __restrict__ ad3,
                          const float* __restrict__ b3,
                          __half* __restrict__ x0h, int* __restrict__ deg, int* __restrict__ goff,
                          __half* __restrict__ w1t, __half* __restrict__ w2t, __half* __restrict__ w3t,
                          float* __restrict__ b3p,
                          float* __restrict__ va1, float* __restrict__ vd1,
                          float* __restrict__ va2, float* __restrict__ vd2,
                          float* __restrict__ va3, float* __restrict__ vd3) {
    int gid = blockIdx.x * blockDim.x + threadIdx.x;
    if (gid < SETUP_A) {
        int n = gid >> 6, d = gid & 63;
        x0h[gid] = __float2half(ne[x[n] * EMB + d] + de[nd[n] * EMB + d]);
        return;
    }
    gid -= SETUP_A;
    if (gid < SETUP_B) {
        int d = (gid < NEDGE) ? ei[NEDGE + gid] : gid - NEDGE;
        atomicAdd(&deg[d], 1);
        return;
    }
    gid -= SETUP_B;
    if (gid < SETUP_C) {            // graph offsets from sorted batch
        int n = gid;
        int c = bat[n];
        if (n == 0) { for (int g = 0; g <= c; g++) goff[g] = 0; }
        else { int p = bat[n - 1]; for (int g = p + 1; g <= c; g++) goff[g] = n; }
        if (n == NNODE - 1) { for (int g = c + 1; g <= NB; g++) goff[g] = NNODE; }
        return;
    }
    gid -= SETUP_C;
    if (gid < SETUP_D) {
        int i = gid;
        if (i < 16384) {
            int h = i >> 12, r = i & 4095, n = r >> 6, k = r & 63;
            w1t[i] = __float2half(w1[k * D1 + h * 64 + n]);
        }
        int j = i - 16384;
        if (j >= 0 && j < 65536) {
            int n = j >> 8, k = j & 255;
            w2t[j] = __float2half(w2[k * D1 + n]);
        }
        int q = i - (16384 + 65536);
        if (q >= 0 && q < H3 * 128 * D1) {
            int h = q >> 15, r = q & 32767, n = r >> 8, k = r & 255;
            w3t[q] = __float2half(n < OUT3 ? w3[k * D3 + h * OUT3 + n] : 0.f);
        }
        if (i < D3P) {
            int h = i >> 7, o = i & 127;
            b3p[i] = (o < OUT3) ? b3[h * OUT3 + o] : 0.f;
        }
        return;
    }
    gid -= SETUP_D;
    if (gid < H12 * EMB) {
        int h = gid >> 6, k = gid & 63;
        float s1 = 0.f, s2 = 0.f;
        for (int d = 0; d < EMB; d++) {
            float w = w1[k * D1 + h * EMB + d];
            s1 += w * as1[h * EMB + d];
            s2 += w * ad1[h * EMB + d];
        }
        va1[gid] = s1; vd1[gid] = s2;
        return;
    }
    gid -= H12 * EMB;
    if (gid < H12 * D1) {
        int h = gid >> 8, k = gid & 255;
        float s1 = 0.f, s2 = 0.f;
        for (int d = 0; d < EMB; d++) {
            float w = w2[k * D1 + h * EMB + d];
            s1 += w * as2[h * EMB + d];
            s2 += w * ad2[h * EMB + d];
        }
        va2[gid] = s1; vd2[gid] = s2;
        return;
    }
    gid -= H12 * D1;
    if (gid < H3 * D1) {
        int h = gid >> 8, k = gid & 255;
        float s1 = 0.f, s2 = 0.f;
        for (int o = 0; o < OUT3; o++) {
            float w = w3[k * D3 + h * OUT3 + o];
            s1 += w * as3[h * OUT3 + o];
            s2 += w * ad3[h * OUT3 + o];
        }
        va3[gid] = s1; vd3[gid] = s2;
    }
}

// ---------------- CSR scan chain ---------------------------------------------
__global__ __launch_bounds__(1024) void deg_part(const int* __restrict__ deg,
                                                 int* __restrict__ bsum) {
    __shared__ int ws[32];
    int t = threadIdx.x, lane = t & 31, w = t >> 5;
    int idx = blockIdx.x * 1024 + t;
    int v = (idx < NNODE) ? deg[idx] : 0;
#pragma unroll
    for (int o = 16; o; o >>= 1) v += __shfl_xor_sync(0xffffffffu, v, o);
    if (lane == 0) ws[w] = v;
    __syncthreads();
    if (t < 32) {
        int s = ws[t];
#pragma unroll
        for (int o = 16; o; o >>= 1) s += __shfl_xor_sync(0xffffffffu, s, o);
        if (t == 0) bsum[blockIdx.x] = s;
    }
}
__global__ void scan_bsum(const int* __restrict__ bsum, int* __restrict__ bpre,
                          int* __restrict__ off, int nblk) {
    int t = threadIdx.x;
    int v = (t < nblk) ? bsum[t] : 0;
    int own = v;
#pragma unroll
    for (int o = 1; o < 32; o <<= 1) {
        int y = __shfl_up_sync(0xffffffffu, v, o);
        if (t >= o) v += y;
    }
    if (t < nblk) bpre[t] = v - own;
    if (t == 31) off[NNODE] = v;
}
__global__ __launch_bounds__(1024) void deg_scan(const int* __restrict__ deg,
                                                 const int* __restrict__ bpre,
                                                 int* __restrict__ off) {
    __shared__ int ws[32];
    int t = threadIdx.x, lane = t & 31, w = t >> 5;
    int idx = blockIdx.x * 1024 + t;
    int v = (idx < NNODE) ? deg[idx] : 0;
    int x = v;
#pragma unroll
    for (int o = 1; o < 32; o <<= 1) {
        int y = __shfl_up_sync(0xffffffffu, x, o);
        if (lane >= o) x += y;
    }
    if (lane == 31) ws[w] = x;
    __syncthreads();
    if (w == 0) {
        int y = ws[lane];
#pragma unroll
        for (int o = 1; o < 32; o <<= 1) {
            int z = __shfl_up_sync(0xffffffffu, y, o);
            if (lane >= o) y += z;
        }
        ws[lane] = y;
    }
    __syncthreads();
    int excl = x - v + (w ? ws[w - 1] : 0) + bpre[blockIdx.x];
    if (idx < NNODE) off[idx] = excl;
}
__global__ void scatter_edges(const int* __restrict__ ei, const int* __restrict__ off,
                              int* __restrict__ cur, int* __restrict__ csrc) {
    int e = blockIdx.x * blockDim.x + threadIdx.x;
    if (e >= ETOT) return;
    int s, d;
    if (e < NEDGE) { s = ei[e]; d = ei[NEDGE + e]; }
    else           { s = d = e - NEDGE; }
    int slot = off[d] + atomicAdd(&cur[d], 1);
    csrc[slot] = s;
}

// ---------------- fp16 tensor GEMM: C = A @ Bt^T -----------------------------
template <int BN>
__global__ __launch_bounds__(256) void gemm_h16(
        const __half* __restrict__ A, const __half* __restrict__ Bt,
        __half* __restrict__ Ch, const float* __restrict__ bias,
        int M, int K, int lda, int ldb, int ldc,
        int aHS, int bHS, int cHS, int biasHS, int elu) {
    constexpr int AST = 40;
    constexpr int WN = BN / 2;
    constexpr int JT = WN / 8;
    __shared__ __half As[128 * AST];
    __shared__ __half Bs[BN * AST];
    int t = threadIdx.x;
    int warp = t >> 5, lane = t & 31;
    int tg = lane >> 2, t4 = lane & 3;
    int bm = blockIdx.y * 128, bn = blockIdx.x * BN;
    int z = blockIdx.z;
    const __half* Az = A + (size_t)aHS * z;
    const __half* Bz = Bt + (size_t)bHS * z;
    int wm = (warp & 3) * 32, wn = (warp >> 2) * WN;
    float c[2][JT][4];
#pragma unroll
    for (int i = 0; i < 2; i++)
#pragma unroll
        for (int j = 0; j < JT; j++)
#pragma unroll
            for (int q = 0; q < 4; q++) c[i][j][q] = 0.f;

    for (int k0 = 0; k0 < K; k0 += 32) {
#pragma unroll
        for (int i = 0; i < 2; i++) {
            int v = t + 256 * i;
            int row = v >> 2, kc = (v & 3) * 8;
            uint4 u = make_uint4(0u, 0u, 0u, 0u);
            int gr = bm + row;
            if (gr < M) u = *(const uint4*)(Az + (size_t)gr * lda + k0 + kc);
            *(uint4*)&As[row * AST + kc] = u;
        }
#pragma unroll
        for (int i = 0; i < BN / 64; i++) {
            int v = t + 256 * i;
            int row = v >> 2, kc = (v & 3) * 8;
            *(uint4*)&Bs[row * AST + kc] =
                *(const uint4*)(Bz + (size_t)(bn + row) * ldb + k0 + kc);
        }
        __syncthreads();
#pragma unroll
        for (int ks = 0; ks < 2; ks++) {
            int kb = ks * 16;
            unsigned a[2][4], b[JT][2];
#pragma unroll
            for (int i = 0; i < 2; i++) {
                int r = wm + 16 * i + tg;
                a[i][0] = *(const unsigned*)&As[r * AST + kb + 2 * t4];
                a[i][1] = *(const unsigned*)&As[(r + 8) * AST + kb + 2 * t4];
                a[i][2] = *(const unsigned*)&As[r * AST + kb + 2 * t4 + 8];
                a[i][3] = *(const unsigned*)&As[(r + 8) * AST + kb + 2 * t4 + 8];
            }
#pragma unroll
            for (int j = 0; j < JT; j++) {
                int n = wn + 8 * j + tg;
                b[j][0] = *(const unsigned*)&Bs[n * AST + kb + 2 * t4];
                b[j][1] = *(const unsigned*)&Bs[n * AST + kb + 2 * t4 + 8];
            }
#pragma unroll
            for (int i = 0; i < 2; i++)
#pragma unroll
                for (int j = 0; j < JT; j++) {
                    asm volatile(
                        "mma.sync.aligned.m16n8k16.row.col.f32.f16.f16.f32 "
                        "{%0,%1,%2,%3}, {%4,%5,%6,%7}, {%8,%9}, {%0,%1,%2,%3};"
                        : "+f"(c[i][j][0]), "+f"(c[i][j][1]),
                          "+f"(c[i][j][2]), "+f"(c[i][j][3])
                        : "r"(a[i][0]), "r"(a[i][1]), "r"(a[i][2]), "r"(a[i][3]),
                          "r"(b[j][0]), "r"(b[j][1]));
                }
        }
        __syncthreads();
    }
#pragma unroll
    for (int i = 0; i < 2; i++)
#pragma unroll
        for (int j = 0; j < JT; j++) {
            int r = bm + wm + 16 * i + tg;
            int cc = bn + wn + 8 * j + 2 * t4;
            float v0 = c[i][j][0], v1 = c[i][j][1];
            float v2 = c[i][j][2], v3 = c[i][j][3];
            if (bias) {
                float b0 = bias[biasHS * z + cc], b1 = bias[biasHS * z + cc + 1];
                v0 += b0; v1 += b1; v2 += b0; v3 += b1;
            }
            if (elu) {
                v0 = v0 > 0.f ? v0 : expm1f(v0);
                v1 = v1 > 0.f ? v1 : expm1f(v1);
                v2 = v2 > 0.f ? v2 : expm1f(v2);
                v3 = v3 > 0.f ? v3 : expm1f(v3);
            }
            __half* Hz = Ch + (size_t)cHS * z;
            if (r < M)     *(__half2*)(Hz + (size_t)r * ldc + cc)       = __floats2half2_rn(v0, v1);
            if (r + 8 < M) *(__half2*)(Hz + (size_t)(r + 8) * ldc + cc) = __floats2half2_rn(v2, v3);
        }
}

// ---------------- attention logits: thread per node, fp16 rows ---------------
template <int K, int H>
__global__ __launch_bounds__(256) void attn_h(const __half* __restrict__ feat,
                                              const float* __restrict__ va,
                                              const float* __restrict__ vd,
                                              float* __restrict__ es,
                                              float* __restrict__ ed) {
    constexpr int K8 = K / 8;
    __shared__ float sva[H * K], svd[H * K];
    int t = threadIdx.x;
    for (int i = t; i < H * K; i += 256) { sva[i] = va[i]; svd[i] = vd[i]; }
    __syncthreads();
    int n = blockIdx.x * 256 + t;
    if (n >= NNODE) return;
    const __half* row = feat + (size_t)n * K;
    float e1[H], e2[H];
#pragma unroll
    for (int h = 0; h < H; h++) { e1[h] = 0.f; e2[h] = 0.f; }
    for (int k8 = 0; k8 < K8; k8++) {
        uint4 u = *(const uint4*)(row + k8 * 8);
        __half2 h0 = *(__half2*)&u.x, h1 = *(__half2*)&u.y;
        __half2 h2 = *(__half2*)&u.z, h3 = *(__half2*)&u.w;
        float xv[8];
        xv[0] = __low2float(h0); xv[1] = __high2float(h0);
        xv[2] = __low2float(h1); xv[3] = __high2float(h1);
        xv[4] = __low2float(h2); xv[5] = __high2float(h2);
        xv[6] = __low2float(h3); xv[7] = __high2float(h3);
#pragma unroll
        for (int h = 0; h < H; h++)
#pragma unroll
            for (int p = 0; p < 8; p++) {
                e1[h] += xv[p] * sva[h * K + k8 * 8 + p];
                e2[h] += xv[p] * svd[h * K + k8 * 8 + p];
            }
    }
#pragma unroll
    for (int h = 0; h < H; h++) {
        es[n * H + h] = e1[h];
        ed[n * H + h] = e2[h];
    }
}

// ---------------- single-pass per-head x aggregation (warp per node) --------
template <int H, int HPL>
__global__ __launch_bounds__(256) void gat_agg_xh(const int* __restrict__ off,
                                                  const int* __restrict__ csrc,
                                                  const float* __restrict__ es,
                                                  const float* __restrict__ ed,
                                                  const __half* __restrict__ xin,
                                                  __half* __restrict__ agg) {
    constexpr int KH = 32 * HPL;
    int gw = (blockIdx.x * blockDim.x + threadIdx.x) >> 5;
    int lane = threadIdx.x & 31;
    if (gw >= NNODE) return;
    int o0 = off[gw], o1 = off[gw + 1];
    float edv = (lane < H) ? __ldg(&ed[gw * H + lane]) : 0.f;
    float smv = 0.f;
    float acc[H][HPL];
#pragma unroll
    for (int h = 0; h < H; h++)
#pragma unroll
        for (int p = 0; p < HPL; p++) acc[h][p] = 0.f;

    for (int i = o0; i < o1; i++) {
        int s = __ldg(&csrc[i]);
        float a = 0.f;
        if (lane < H) {
            float v = __ldg(&es[s * H + lane]) + edv;
            v = v > 0.f ? v : 0.2f * v;
            a = __expf(v);
            smv += a;
        }
        float ah[H];
#pragma unroll
        for (int h = 0; h < H; h++) ah[h] = __shfl_sync(0xffffffffu, a, h);
        const __half* row = xin + (size_t)s * KH + lane * HPL;
        float xv[HPL];
        if (HPL == 2) {
            __half2 hv = *(const __half2*)row;
            xv[0] = __low2float(hv); xv[1] = __high2float(hv);
        } else {
            uint4 u = *(const uint4*)row;
            __half2 h0 = *(__half2*)&u.x, h1 = *(__half2*)&u.y;
            __half2 h2 = *(__half2*)&u.z, h3 = *(__half2*)&u.w;
            xv[0] = __low2float(h0); xv[1] = __high2float(h0);
            xv[2] = __low2float(h1); xv[3] = __high2float(h1);
            xv[4] = __low2float(h2); xv[5] = __high2float(h2);
            xv[6] = __low2float(h3); xv[7] = __high2float(h3);
        }
#pragma unroll
        for (int h = 0; h < H; h++)
#pragma unroll
            for (int p = 0; p < HPL; p++) acc[h][p] += ah[h] * xv[p];
    }
    float inv[H];
#pragma unroll
    for (int h = 0; h < H; h++)
        inv[h] = 1.f / __shfl_sync(0xffffffffu, smv, h);
    __half* orow = agg + (size_t)gw * (H * KH);
#pragma unroll
    for (int h = 0; h < H; h++)
#pragma unroll
        for (int p = 0; p < HPL; p += 2)
            *(__half2*)(orow + h * KH + lane * HPL + p) =
                __floats2half2_rn(acc[h][p] * inv[h], acc[h][p + 1] * inv[h]);
}

// ---------------- single-pass layer-2 aggregation (fp16 out) -----------------
__global__ __launch_bounds__(256) void gat_agg_ph(const int* __restrict__ off,
                                                  const int* __restrict__ csrc,
                                                  const float* __restrict__ es,
                                                  const float* __restrict__ ed,
                                                  const __half* __restrict__ proj,
                                                  const float* __restrict__ bias,
                                                  __half* __restrict__ outh) {
    constexpr int H = H12;
    int gw = (blockIdx.x * blockDim.x + threadIdx.x) >> 5;
    int lane = threadIdx.x & 31;
    if (gw >= NNODE) return;
    int o0 = off[gw], o1 = off[gw + 1];
    float edv = (lane < H) ? __ldg(&ed[gw * H + lane]) : 0.f;
    float smv = 0.f;
    float acc[8];
#pragma unroll
    for (int p = 0; p < 8; p++) acc[p] = 0.f;
    int myhead = lane >> 3;

    for (int i = o0; i < o1; i++) {
        int s = __ldg(&csrc[i]);
        float a = 0.f;
        if (lane < H) {
            float v = __ldg(&es[s * H + lane]) + edv;
            v = v > 0.f ? v : 0.2f * v;
            a = __expf(v);
            smv += a;
        }
        float av = __shfl_sync(0xffffffffu, a, myhead);
        uint4 u = *(const uint4*)(proj + (size_t)s * D1 + lane * 8);
        __half2 h0 = *(__half2*)&u.x, h1 = *(__half2*)&u.y;
        __half2 h2 = *(__half2*)&u.z, h3 = *(__half2*)&u.w;
        acc[0] += av * __low2float(h0); acc[1] += av * __high2float(h0);
        acc[2] += av * __low2float(h1); acc[3] += av * __high2float(h1);
        acc[4] += av * __low2float(h2); acc[5] += av * __high2float(h2);
        acc[6] += av * __low2float(h3); acc[7] += av * __high2float(h3);
    }
    float inv = 1.f / __shfl_sync(0xffffffffu, smv, myhead);
    __half* hrow = outh + (size_t)gw * D1 + lane * 8;
#pragma unroll
    for (int p = 0; p < 8; p += 2) {
        float v0 = acc[p] * inv + bias[lane * 8 + p];
        float v1 = acc[p + 1] * inv + bias[lane * 8 + p + 1];
        v0 = v0 > 0.f ? v0 : expm1f(v0);
        v1 = v1 > 0.f ? v1 : expm1f(v1);
        *(__half2*)(hrow + p) = __floats2half2_rn(v0, v1);
    }
}

// ---------------- streaming per-graph pool of agg3h (n-unrolled x2) ----------
__global__ __launch_bounds__(256) void pool_seg(const int* __restrict__ goff,
                                                const __half* __restrict__ agg,
                                                float* __restrict__ poolx) {
    constexpr int NCOL = H3 * D1;    // 1536
    int b = blockIdx.x;
    int t = threadIdx.x;
    int n0 = goff[b], n1 = goff[b + 1];
    float acc[NCOL / 256];           // 6
#pragma unroll
    for (int j = 0; j < NCOL / 256; j++) acc[j] = 0.f;
    int n = n0;
    for (; n + 1 < n1; n += 2) {
        const __half* r0 = agg + (size_t)n * NCOL;
        const __half* r1 = r0 + NCOL;
#pragma unroll
        for (int j = 0; j < NCOL / 256; j++)
            acc[j] += __half2float(__ldg(&r0[t + 256 * j]))
                    + __half2float(__ldg(&r1[t + 256 * j]));
    }
    if (n < n1) {
        const __half* r0 = agg + (size_t)n * NCOL;
#pragma unroll
        for (int j = 0; j < NCOL / 256; j++)
            acc[j] += __half2float(__ldg(&r0[t + 256 * j]));
    }
    float* orow = poolx + (size_t)b * NCOL;
#pragma unroll
    for (int j = 0; j < NCOL / 256; j++) orow[t + 256 * j] = acc[j];
}

// ---------------- projection: poolx [NB,6,256] @ w3t -> pool [NB,768] --------
// grid (NB, H3), 128 threads; poolx row in smem (broadcast); k fully unrolled,
// 4 independent accumulators. Weight reads uint4 from L2.
__global__ __launch_bounds__(128) void proj_pool(const float* __restrict__ poolx,
                                                 const __half* __restrict__ w3t,
                                                 float* __restrict__ pool) {
    __shared__ float px[D1];
    int b = blockIdx.x, h = blockIdx.y;
    int c = threadIdx.x;
    const float* prow = poolx + (size_t)b * (H3 * D1) + h * D1;
    px[c] = prow[c];
    px[c + 128] = prow[c + 128];
    __syncthreads();
    const __half* wrow = w3t + (size_t)h * (128 * D1) + (size_t)c * D1;
    float a0 = 0.f, a1 = 0.f, a2 = 0.f, a3 = 0.f;
#pragma unroll
    for (int k = 0; k < D1; k += 32) {
        uint4 u0 = *(const uint4*)(wrow + k);
        uint4 u1 = *(const uint4*)(wrow + k + 8);
        uint4 u2 = *(const uint4*)(wrow + k + 16);
        uint4 u3 = *(const uint4*)(wrow + k + 24);
        const __half2* h0 = (const __half2*)&u0;
        const __half2* h1 = (const __half2*)&u1;
        const __half2* h2 = (const __half2*)&u2;
        const __half2* h3 = (const __half2*)&u3;
#pragma unroll
        for (int q = 0; q < 4; q++) {
            a0 += px[k + 2 * q]          * __low2float(h0[q]) + px[k + 2 * q + 1]      * __high2float(h0[q]);
            a1 += px[k + 8 + 2 * q]      * __low2float(h1[q]) + px[k + 8 + 2 * q + 1]  * __high2float(h1[q]);
            a2 += px[k + 16 + 2 * q]     * __low2float(h2[q]) + px[k + 16 + 2 * q + 1] * __high2float(h2[q]);
            a3 += px[k + 24 + 2 * q]     * __low2float(h3[q]) + px[k + 24 + 2 * q + 1] * __high2float(h3[q]);
        }
    }
    pool[(size_t)b * D3P + h * 128 + c] = (a0 + a1) + (a2 + a3);
}

// ---------------- classifier head --------------------------------------------
__global__ void head_kernel(const float* __restrict__ pool, const int* __restrict__ goff,
                            const float* __restrict__ b3p,
                            const float* __restrict__ wp, const float* __restrict__ bp,
                            float* __restrict__ out) {
    __shared__ float gm[OUT3];
    int b = blockIdx.x;
    float cn = (float)(goff[b + 1] - goff[b]);
    float inv = 1.f / fmaxf(cn, 1.f);
    for (int o = threadIdx.x; o < OUT3; o += blockDim.x) {
        float s = 0.f, sb = 0.f;
#pragma unroll
        for (int h = 0; h < H3; h++) {
            s += pool[b * D3P + h * 128 + o];
            sb += b3p[h * 128 + o];
        }
        gm[o] = (s * inv + sb) * (1.f / H3);
    }
    __syncthreads();
    if (threadIdx.x < NCLS) {
        float acc = bp[threadIdx.x];
        for (int o = 0; o < OUT3; o++) acc += gm[o] * wp[o * NCLS + threadIdx.x];
        out[b * NCLS + threadIdx.x] = acc;
    }
}

// ---------------- host orchestration ----------------------------------------
extern "C" void kernel_launch(void* const* d_in, const int* in_sizes, int n_in,
                              void* d_out, int out_size) {
    const int*   x    = (const int*)d_in[0];
    const int*   nd   = (const int*)d_in[1];
    const int*   ei   = (const int*)d_in[2];
    const int*   bat  = (const int*)d_in[3];
    const float* nemb = (const float*)d_in[4];
    const float* demb = (const float*)d_in[5];
    const float* w1   = (const float*)d_in[6];
    const float* as1  = (const float*)d_in[7];
    const float* ad1  = (const float*)d_in[8];
    const float* b1   = (const float*)d_in[9];
    const float* w2   = (const float*)d_in[10];
    const float* as2  = (const float*)d_in[11];
    const float* ad2  = (const float*)d_in[12];
    const float* b2   = (const float*)d_in[13];
    const float* w3   = (const float*)d_in[14];
    const float* as3  = (const float*)d_in[15];
    const float* ad3  = (const float*)d_in[16];
    const float* b3   = (const float*)d_in[17];
    const float* wp   = (const float*)d_in[18];
    const float* bp   = (const float*)d_in[19];
    float* out = (float*)d_out;

    float *es, *ed, *va1, *vd1, *va2, *vd2, *va3, *vd3, *b3p, *poolx, *pool;
    __half *x0h, *p1h, *feath, *projh, *feat2h, *agg3h, *w1t, *w2t, *w3t;
    int *deg, *off, *goff, *cur, *csrc, *bsum, *bpre;
    cudaGetSymbolAddress((void**)&x0h,   g_x0h);
    cudaGetSymbolAddress((void**)&p1h,   g_p1h);
    cudaGetSymbolAddress((void**)&feath, g_feath);
    cudaGetSymbolAddress((void**)&projh, g_projh);
    cudaGetSymbolAddress((void**)&feat2h,g_feat2h);
    cudaGetSymbolAddress((void**)&agg3h, g_agg3h);
    cudaGetSymbolAddress((void**)&es,    g_es);
    cudaGetSymbolAddress((void**)&ed,    g_ed);
    cudaGetSymbolAddress((void**)&va1,   g_va1);
    cudaGetSymbolAddress((void**)&vd1,   g_vd1);
    cudaGetSymbolAddress((void**)&va2,   g_va2);
    cudaGetSymbolAddress((void**)&vd2,   g_vd2);
    cudaGetSymbolAddress((void**)&va3,   g_va3);
    cudaGetSymbolAddress((void**)&vd3,   g_vd3);
    cudaGetSymbolAddress((void**)&w1t,   g_w1t);
    cudaGetSymbolAddress((void**)&w2t,   g_w2t);
    cudaGetSymbolAddress((void**)&w3t,   g_w3t);
    cudaGetSymbolAddress((void**)&b3p,   g_b3p);
    cudaGetSymbolAddress((void**)&poolx, g_poolx);
    cudaGetSymbolAddress((void**)&pool,  g_pool);
    cudaGetSymbolAddress((void**)&deg,   g_deg);
    cudaGetSymbolAddress((void**)&off,   g_off);
    cudaGetSymbolAddress((void**)&goff,  g_goff);
    cudaGetSymbolAddress((void**)&cur,   g_cur);
    cudaGetSymbolAddress((void**)&csrc,  g_csrc);
    cudaGetSymbolAddress((void**)&bsum,  g_bsum);
    cudaGetSymbolAddress((void**)&bpre,  g_bpre);

    const int TB = 256;
    const int eb = (ETOT + TB - 1) / TB;
    const int nb = (NNODE * 32 + TB - 1) / TB;   // warp per node
    const int hb = (NNODE + TB - 1) / TB;        // thread per node
    const int SB = (NNODE + 1023) / 1024;
    const int MB = (NNODE + 127) / 128;

    cudaMemsetAsync(deg, 0, NNODE * 4);
    cudaMemsetAsync(cur, 0, NNODE * 4);

    setup_all<<<(SETUP_TOTAL + TB - 1) / TB, TB>>>(
        x, nd, nemb, demb, ei, bat,
        w1, as1, ad1, w2, as2, ad2, w3, as3, ad3, b3,
        x0h, deg, goff, w1t, w2t, w3t, b3p,
        va1, vd1, va2, vd2, va3, vd3);
    deg_part<<<SB, 1024>>>(deg, bsum);
    scan_bsum<<<1, 32>>>(bsum, bpre, off, SB);
    deg_scan<<<SB, 1024>>>(deg, bpre, off);
    scatter_edges<<<eb, TB>>>(ei, off, cur, csrc);

    // ---- layer 1 ----
    attn_h<EMB, H12><<<hb, TB>>>(x0h, va1, vd1, es, ed);
    gat_agg_xh<H12, 2><<<nb, TB>>>(off, csrc, es, ed, x0h, p1h);
    {
        dim3 g(1, MB, H12);
        gemm_h16<64><<<g, 256>>>(p1h, w1t, feath, b1, NNODE, EMB,
                                 D1, EMB, D1, EMB, 64 * EMB, EMB, EMB, 1);
    }

    // ---- layer 2 ----
    {
        dim3 g(2, MB, 1);
        gemm_h16<128><<<g, 256>>>(feath, w2t, projh, nullptr, NNODE, D1,
                                  D1, D1, D1, 0, 0, 0, 0, 0);
    }
    attn_h<D1, H12><<<hb, TB>>>(feath, va2, vd2, es, ed);
    gat_agg_ph<<<nb, TB>>>(off, csrc, es, ed, projh, b2, feat2h);

    // ---- layer 3: warp-per-node aggregate, streaming pool, fixed projection -
    attn_h<D1, H3><<<hb, TB>>>(feat2h, va3, vd3, es, ed);
    gat_agg_xh<H3, 8><<<nb, TB>>>(off, csrc, es, ed, feat2h, agg3h);
    pool_seg<<<NB, TB>>>(goff, agg3h, poolx);
    {
        dim3 g(NB, H3);
        proj_pool<<<g, 128>>>(poolx, w3t, pool);
    }

    // ---- classifier head ----
    head_kernel<<<NB, 128>>>(pool, goff, b3p, wp, bp, out);
}